// round 8
// baseline (speedup 1.0000x reference)
#include <cuda_runtime.h>

// Problem constants (from reference setup_inputs)
#define B_    256
#define J_    17
#define HW_   6912             // 96*72
#define BJ_   (B_ * J_)        // 4352
#define HALF4_ 864             // float4 per half-slice (HW_/4/2)
#define NCHUNK (BJ_ * 2)       // 8704 half-slices
#define GRIDA  (NCHUNK / 8)    // 1088 blocks x 8 warps = one chunk per warp

// Transposed partials: g_partials[j*512 + b*2 + h]  (512 contiguous per joint)
__device__ float        g_partials[NCHUNK];
__device__ unsigned int g_done = 0;    // reset by finisher each run

// ---------------------------------------------------------------------------
// Fused kernel, warp-granular streaming:
//  - one half-slice per warp, 27 exact iterations, NO block barriers,
//    no shared memory, no CTA churn (single resident wave of 1088 blocks)
//  - per-warp epilogue: shuffle-reduce + store + red.release (fire-and-forget)
//  - block 0 is the finisher (R7 protocol, proven correct & ~free)
// ---------------------------------------------------------------------------
__global__ __launch_bounds__(256) void jmse_fused_kernel(
    const float* __restrict__ out,
    const float* __restrict__ tgt,
    const float* __restrict__ wgt,
    const int*  __restrict__ topk_ptr,
    float*      __restrict__ result)
{
    const int lane = threadIdx.x & 31;
    const int wid  = threadIdx.x >> 5;

    // ---- streaming phase: one half-slice per warp ----
    {
        const int c  = blockIdx.x * 8 + wid;     // 0..8703
        const int bj = c >> 1;
        const int h  = c & 1;
        const size_t base4 = (size_t)bj * (HW_ / 4) + (size_t)h * HALF4_;
        const float4* __restrict__ o4 = (const float4*)out + base4;
        const float4* __restrict__ t4 = (const float4*)tgt + base4;

        float acc = 0.0f;
        #pragma unroll 3
        for (int i = lane; i < HALF4_; i += 32) {   // exactly 27 iterations
            float4 a = o4[i];
            float4 b = t4[i];
            float d0 = a.x - b.x;
            float d1 = a.y - b.y;
            float d2 = a.z - b.z;
            float d3 = a.w - b.w;
            acc = fmaf(d0, d0, acc);
            acc = fmaf(d1, d1, acc);
            acc = fmaf(d2, d2, acc);
            acc = fmaf(d3, d3, acc);
        }

        #pragma unroll
        for (int off = 16; off > 0; off >>= 1)
            acc += __shfl_xor_sync(0xFFFFFFFFu, acc, off);

        if (lane == 0) {
            const float w = wgt[bj];                     // [B, J, 1] contiguous
            const int b = bj / J_;
            const int j = bj - b * J_;
            g_partials[j * (B_ * 2) + b * 2 + h] = acc * w * w;
            // Fire-and-forget release increment: orders the store above,
            // no MEMBAR drain, no return value.
            asm volatile("red.release.gpu.global.add.u32 [%0], 1;"
                         :: "l"(&g_done) : "memory");
        }
    }

    if (blockIdx.x != 0) return;

    // ---- finisher (block 0 only) ----
    if (threadIdx.x == 0) {
        unsigned int v;
        do {
            asm volatile("ld.acquire.gpu.global.u32 %0, [%1];"
                         : "=r"(v) : "l"(&g_done));
            if (v < (unsigned)NCHUNK) __nanosleep(100);
        } while (v < (unsigned)NCHUNK);
    }
    __syncthreads();   // all 8 warps proceed once everything is visible

    // 8 warps; warp w reduces joints w, w+8, w+16.
    // 512 floats per joint = 128 float4; 4 per lane.
    __shared__ float losses[J_];
    for (int j = wid; j < J_; j += 8) {
        const float4* p4 = (const float4*)&g_partials[j * (B_ * 2)];
        float4 a = __ldcg(p4 + lane);
        float4 b = __ldcg(p4 + lane + 32);
        float4 cc = __ldcg(p4 + lane + 64);
        float4 d = __ldcg(p4 + lane + 96);
        float s = ((a.x + a.y) + (a.z + a.w)) + ((b.x + b.y) + (b.z + b.w))
                + ((cc.x + cc.y) + (cc.z + cc.w)) + ((d.x + d.y) + (d.z + d.w));
        #pragma unroll
        for (int off = 16; off > 0; off >>= 1)
            s += __shfl_xor_sync(0xFFFFFFFFu, s, off);
        if (lane == 0)
            losses[j] = s * (1.0f / ((float)B_ * (float)HW_));
    }
    __syncthreads();

    if (threadIdx.x == 0) {
        const int k = *topk_ptr;
        float v[J_];
        #pragma unroll
        for (int j = 0; j < J_; j++) v[j] = losses[j];
        float sum = 0.0f;
        for (int s = 0; s < k; s++) {
            int   best_i = 0;
            float best_v = v[0];
            #pragma unroll
            for (int j = 1; j < J_; j++)
                if (v[j] > best_v) { best_v = v[j]; best_i = j; }
            sum += best_v;
            v[best_i] = -3.402823466e38f;
        }
        result[0] = sum / (float)k;
        g_done = 0;   // reset for next graph replay
    }
}

// ---------------------------------------------------------------------------
extern "C" void kernel_launch(void* const* d_in, const int* in_sizes, int n_in,
                              void* d_out, int out_size)
{
    const float* out_t = (const float*)d_in[0];
    const float* tgt_t = (const float*)d_in[1];
    const float* wgt_t = (const float*)d_in[2];
    const int*   topk  = (const int*)d_in[3];
    float* res = (float*)d_out;

    jmse_fused_kernel<<<GRIDA, 256>>>(out_t, tgt_t, wgt_t, topk, res);
}

// round 9
// speedup vs baseline: 1.0296x; 1.0296x over previous
#include <cuda_runtime.h>
#include <cstdint>

// Problem constants (from reference setup_inputs)
#define B_    256
#define J_    17
#define HW_   6912                      // 96*72 floats per (b,j) slice
#define BJ_   (B_ * J_)                 // 4352 slices
#define SLICE_BYTES  (HW_ * 4)          // 27648 B per slice per tensor
#define NCHUNK_      6
#define CHUNK_BYTES  (SLICE_BYTES / NCHUNK_)   // 4608 B
#define CHUNK_F4     (CHUNK_BYTES / 16)        // 288 float4 -> 1 per thread
#define NSTAGE_      4
#define THREADS_     288                // 9 warps; 1 float4/thread/array/chunk

__device__ float        g_partials[BJ_];       // transposed: [j*256 + b]
__device__ unsigned int g_done = 0;            // reset by finisher each run

__device__ __forceinline__ uint32_t smem_u32(const void* p) {
    uint32_t a;
    asm("{ .reg .u64 t; cvta.to.shared.u64 t, %1; cvt.u32.u64 %0, t; }"
        : "=r"(a) : "l"(p));
    return a;
}

__device__ __forceinline__ void mbar_wait_parity(uint32_t mb, uint32_t parity) {
    uint32_t done;
    asm volatile(
        "{\n\t.reg .pred p;\n\t"
        "mbarrier.try_wait.parity.acquire.cta.shared::cta.b64 p, [%1], %2;\n\t"
        "selp.b32 %0, 1, 0, p;\n\t}"
        : "=r"(done) : "r"(mb), "r"(parity) : "memory");
    if (!done) {
        asm volatile(
            "{\n\t.reg .pred P1;\n\t"
            "W_%=:\n\t"
            "mbarrier.try_wait.parity.acquire.cta.shared::cta.b64 P1, [%0], %1, 0x989680;\n\t"
            "@P1 bra.uni D_%=;\n\t"
            "bra.uni W_%=;\n\t"
            "D_%=:\n\t}"
            :: "r"(mb), "r"(parity) : "memory");
    }
}

__device__ __forceinline__ void issue_chunk(
    uint32_t mb, uint32_t dst_o, uint32_t dst_t,
    const char* src_o, const char* src_t)
{
    asm volatile("mbarrier.arrive.expect_tx.shared.b64 _, [%0], %1;"
                 :: "r"(mb), "r"(2u * CHUNK_BYTES) : "memory");
    asm volatile("cp.async.bulk.shared::cta.global.mbarrier::complete_tx::bytes "
                 "[%0], [%1], %2, [%3];"
                 :: "r"(dst_o), "l"(src_o), "r"((uint32_t)CHUNK_BYTES), "r"(mb)
                 : "memory");
    asm volatile("cp.async.bulk.shared::cta.global.mbarrier::complete_tx::bytes "
                 "[%0], [%1], %2, [%3];"
                 :: "r"(dst_t), "l"(src_t), "r"((uint32_t)CHUNK_BYTES), "r"(mb)
                 : "memory");
}

// ---------------------------------------------------------------------------
// TMA-pipelined fused kernel. One (b,j) slice per CTA, 4-deep bulk-copy
// pipeline into smem; per-SM in-flight bytes ~220KB (vs ~32KB LDG cap).
// Block 0 is the finisher (R7 red.release + acquire-spin protocol).
// ---------------------------------------------------------------------------
__global__ __launch_bounds__(THREADS_) void jmse_tma_kernel(
    const float* __restrict__ out,
    const float* __restrict__ tgt,
    const float* __restrict__ wgt,
    const int*  __restrict__ topk_ptr,
    float*      __restrict__ result)
{
    __shared__ __align__(128) float4 s_o[NSTAGE_][CHUNK_F4];
    __shared__ __align__(128) float4 s_t[NSTAGE_][CHUNK_F4];
    __shared__ __align__(8)   unsigned long long s_mbar[NSTAGE_];
    __shared__ float warp_sums[THREADS_ / 32];

    const int tid  = threadIdx.x;
    const int lane = tid & 31;
    const int wid  = tid >> 5;
    const int bj   = blockIdx.x;

    const char* go = (const char*)(out + (size_t)bj * HW_);
    const char* gt = (const char*)(tgt + (size_t)bj * HW_);

    const uint32_t mbar0 = smem_u32(&s_mbar[0]);

    if (tid == 0) {
        #pragma unroll
        for (int s = 0; s < NSTAGE_; s++)
            asm volatile("mbarrier.init.shared.b64 [%0], 1;"
                         :: "r"(mbar0 + s * 8) : "memory");
        asm volatile("fence.proxy.async.shared::cta;" ::: "memory");
    }
    __syncthreads();

    // Prologue: fill all 4 stages (chunks 0..3)
    if (tid == 0) {
        #pragma unroll
        for (int s = 0; s < NSTAGE_; s++)
            issue_chunk(mbar0 + s * 8,
                        smem_u32(&s_o[s][0]), smem_u32(&s_t[s][0]),
                        go + s * CHUNK_BYTES, gt + s * CHUNK_BYTES);
    }

    // Mainloop: 6 chunks, stage = c&3, parity flips on reuse
    float acc = 0.0f;
    for (int c = 0; c < NCHUNK_; c++) {
        const int st = c & 3;
        const uint32_t parity = (c < NSTAGE_) ? 0u : 1u;
        mbar_wait_parity(mbar0 + st * 8, parity);

        float4 a = s_o[st][tid];
        float4 b = s_t[st][tid];
        float d0 = a.x - b.x;
        float d1 = a.y - b.y;
        float d2 = a.z - b.z;
        float d3 = a.w - b.w;
        acc = fmaf(d0, d0, acc);
        acc = fmaf(d1, d1, acc);
        acc = fmaf(d2, d2, acc);
        acc = fmaf(d3, d3, acc);

        __syncthreads();    // stage fully consumed before reissue
        if (tid == 0 && c + NSTAGE_ < NCHUNK_) {
            const int n = c + NSTAGE_;
            issue_chunk(mbar0 + st * 8,
                        smem_u32(&s_o[st][0]), smem_u32(&s_t[st][0]),
                        go + n * CHUNK_BYTES, gt + n * CHUNK_BYTES);
        }
    }

    // Block reduce (9 warps)
    #pragma unroll
    for (int off = 16; off > 0; off >>= 1)
        acc += __shfl_xor_sync(0xFFFFFFFFu, acc, off);
    if (lane == 0) warp_sums[wid] = acc;
    __syncthreads();

    if (tid == 0) {
        float s = 0.0f;
        #pragma unroll
        for (int w9 = 0; w9 < THREADS_ / 32; w9++) s += warp_sums[w9];
        const float w = wgt[bj];                 // [B, J, 1] contiguous
        const int b = bj / J_;
        const int j = bj - b * J_;
        g_partials[j * B_ + b] = s * w * w;      // transposed store
        asm volatile("red.release.gpu.global.add.u32 [%0], 1;"
                     :: "l"(&g_done) : "memory");
    }

    if (blockIdx.x != 0) return;

    // ---- finisher (block 0 only), R7 protocol ----
    if (tid == 0) {
        unsigned int v;
        do {
            asm volatile("ld.acquire.gpu.global.u32 %0, [%1];"
                         : "=r"(v) : "l"(&g_done));
            if (v < (unsigned)BJ_) __nanosleep(100);
        } while (v < (unsigned)BJ_);
    }
    __syncthreads();

    __shared__ float losses[J_];
    for (int j = wid; j < J_; j += THREADS_ / 32) {
        // 256 floats per joint = 64 float4, 2 per lane
        const float4* p4 = (const float4*)&g_partials[j * B_];
        float4 a = __ldcg(p4 + lane);
        float4 b = __ldcg(p4 + lane + 32);
        float s = (a.x + a.y) + (a.z + a.w) + (b.x + b.y) + (b.z + b.w);
        #pragma unroll
        for (int off = 16; off > 0; off >>= 1)
            s += __shfl_xor_sync(0xFFFFFFFFu, s, off);
        if (lane == 0)
            losses[j] = s * (1.0f / ((float)B_ * (float)HW_));
    }
    __syncthreads();

    if (tid == 0) {
        const int k = *topk_ptr;
        float v[J_];
        #pragma unroll
        for (int j = 0; j < J_; j++) v[j] = losses[j];
        float sum = 0.0f;
        for (int s = 0; s < k; s++) {
            int   best_i = 0;
            float best_v = v[0];
            #pragma unroll
            for (int j = 1; j < J_; j++)
                if (v[j] > best_v) { best_v = v[j]; best_i = j; }
            sum += best_v;
            v[best_i] = -3.402823466e38f;
        }
        result[0] = sum / (float)k;
        g_done = 0;   // reset for next graph replay
    }
}

// ---------------------------------------------------------------------------
extern "C" void kernel_launch(void* const* d_in, const int* in_sizes, int n_in,
                              void* d_out, int out_size)
{
    const float* out_t = (const float*)d_in[0];
    const float* tgt_t = (const float*)d_in[1];
    const float* wgt_t = (const float*)d_in[2];
    const int*   topk  = (const int*)d_in[3];
    float* res = (float*)d_out;

    jmse_tma_kernel<<<BJ_, THREADS_>>>(out_t, tgt_t, wgt_t, topk, res);
}

// round 10
// speedup vs baseline: 1.0929x; 1.0614x over previous
#include <cuda_runtime.h>

// Problem constants (from reference setup_inputs)
#define B_    256
#define J_    17
#define HW_   6912            // 96*72
#define V4_   (HW_ / 4)       // 1728 float4 per (b,j) slice
#define BJ_   (B_ * J_)       // 4352
#define TPB_  288             // 1728 / 288 = exactly 6 iterations, no ragged tail

// Scratch: transposed partials, g_partials[j * B_ + b] (contiguous per joint)
__device__ float g_partials[BJ_];

// ---------------------------------------------------------------------------
// Kernel A: one block per (b,j) slice, 288 threads, exact 6-iter unrolled
// stream. PDL trigger fired at entry so kernel B launches immediately.
// ---------------------------------------------------------------------------
__global__ __launch_bounds__(TPB_) void jmse_partial_kernel(
    const float* __restrict__ out,
    const float* __restrict__ tgt,
    const float* __restrict__ wgt)
{
    asm volatile("griddepcontrol.launch_dependents;");

    const int bj = blockIdx.x;
    const size_t base = (size_t)bj * HW_;
    const float4* __restrict__ o4 = (const float4*)(out + base);
    const float4* __restrict__ t4 = (const float4*)(tgt + base);

    float acc = 0.0f;
    #pragma unroll
    for (int k = 0; k < 6; k++) {          // exact: 6 * 288 = 1728
        const int i = threadIdx.x + k * TPB_;
        float4 a = o4[i];
        float4 b = t4[i];
        float d0 = a.x - b.x;
        float d1 = a.y - b.y;
        float d2 = a.z - b.z;
        float d3 = a.w - b.w;
        acc = fmaf(d0, d0, acc);
        acc = fmaf(d1, d1, acc);
        acc = fmaf(d2, d2, acc);
        acc = fmaf(d3, d3, acc);
    }

    // warp reduce
    #pragma unroll
    for (int off = 16; off > 0; off >>= 1)
        acc += __shfl_xor_sync(0xFFFFFFFFu, acc, off);

    __shared__ float warp_sums[TPB_ / 32];   // 9 warps
    const int lane = threadIdx.x & 31;
    const int wid  = threadIdx.x >> 5;
    if (lane == 0) warp_sums[wid] = acc;
    __syncthreads();

    if (threadIdx.x == 0) {
        float s = 0.0f;
        #pragma unroll
        for (int w9 = 0; w9 < TPB_ / 32; w9++) s += warp_sums[w9];
        const float w = wgt[bj];                 // [B, J, 1] contiguous
        const int b = bj / J_;
        const int j = bj - b * J_;
        g_partials[j * B_ + b] = s * w * w;      // transposed store
    }
}

// ---------------------------------------------------------------------------
// Kernel B (PDL secondary): 17 warps, one per joint; contiguous float4 loads.
// ---------------------------------------------------------------------------
__global__ __launch_bounds__(544) void jmse_final_kernel(
    const int* __restrict__ topk_ptr,
    float* __restrict__ result)
{
    __shared__ float losses[J_];
    const int wid  = threadIdx.x >> 5;   // 0..16
    const int lane = threadIdx.x & 31;

    // Park until primary grid completes; its writes are then visible.
    asm volatile("griddepcontrol.wait;");

    if (wid < J_) {
        // 256 floats per joint = 64 float4, 2 per lane
        const float4* p4 = (const float4*)&g_partials[wid * B_];
        float4 a = p4[lane];
        float4 b = p4[lane + 32];
        float s = (a.x + a.y) + (a.z + a.w) + (b.x + b.y) + (b.z + b.w);
        #pragma unroll
        for (int off = 16; off > 0; off >>= 1)
            s += __shfl_xor_sync(0xFFFFFFFFu, s, off);
        if (lane == 0)
            losses[wid] = s * (1.0f / ((float)B_ * (float)HW_));
    }
    __syncthreads();

    if (threadIdx.x == 0) {
        const int k = *topk_ptr;
        float v[J_];
        #pragma unroll
        for (int j = 0; j < J_; j++) v[j] = losses[j];
        float sum = 0.0f;
        for (int s = 0; s < k; s++) {
            int   best_i = 0;
            float best_v = v[0];
            #pragma unroll
            for (int j = 1; j < J_; j++)
                if (v[j] > best_v) { best_v = v[j]; best_i = j; }
            sum += best_v;
            v[best_i] = -3.402823466e38f;
        }
        result[0] = sum / (float)k;
    }
}

// ---------------------------------------------------------------------------
extern "C" void kernel_launch(void* const* d_in, const int* in_sizes, int n_in,
                              void* d_out, int out_size)
{
    const float* out_t = (const float*)d_in[0];
    const float* tgt_t = (const float*)d_in[1];
    const float* wgt_t = (const float*)d_in[2];
    const int*   topk  = (const int*)d_in[3];
    float* res = (float*)d_out;

    jmse_partial_kernel<<<BJ_, TPB_>>>(out_t, tgt_t, wgt_t);

    cudaLaunchConfig_t cfg = {};
    cfg.gridDim  = dim3(1, 1, 1);
    cfg.blockDim = dim3(544, 1, 1);
    cfg.dynamicSmemBytes = 0;
    cfg.stream = 0;
    cudaLaunchAttribute attr[1];
    attr[0].id = cudaLaunchAttributeProgrammaticStreamSerialization;
    attr[0].val.programmaticStreamSerializationAllowed = 1;
    cfg.attrs = attr;
    cfg.numAttrs = 1;
    cudaLaunchKernelEx(&cfg, jmse_final_kernel, topk, res);
}

// round 11
// speedup vs baseline: 1.1005x; 1.0070x over previous
#include <cuda_runtime.h>

// Problem constants (from reference setup_inputs)
#define B_    256
#define J_    17
#define HW_   6912            // 96*72
#define V4_   (HW_ / 4)       // 1728 float4 per (b,j) slice
#define BJ_   (B_ * J_)       // 4352
#define TPB_  288             // 1728 / 288 = exactly 6 iterations, no ragged tail

// Scratch: transposed partials, g_partials[j * B_ + b] (contiguous per joint)
__device__ float g_partials[BJ_];

// ---------------------------------------------------------------------------
// Kernel A: one block per (b,j) slice, 288 threads, exact 6-iter unrolled
// stream. PDL trigger fired at entry; weight load hoisted to overlap stream.
// ---------------------------------------------------------------------------
__global__ __launch_bounds__(TPB_) void jmse_partial_kernel(
    const float* __restrict__ out,
    const float* __restrict__ tgt,
    const float* __restrict__ wgt)
{
    asm volatile("griddepcontrol.launch_dependents;");

    const int bj = blockIdx.x;

    // Hoisted: issue the scalar weight load now so it's resolved long before
    // the epilogue (the last block's epilogue sits on the critical path).
    float w_early = 0.0f;
    if (threadIdx.x == 0) w_early = __ldg(&wgt[bj]);

    const size_t base = (size_t)bj * HW_;
    const float4* __restrict__ o4 = (const float4*)(out + base);
    const float4* __restrict__ t4 = (const float4*)(tgt + base);

    float acc = 0.0f;
    #pragma unroll
    for (int k = 0; k < 6; k++) {          // exact: 6 * 288 = 1728
        const int i = threadIdx.x + k * TPB_;
        float4 a = o4[i];
        float4 b = t4[i];
        float d0 = a.x - b.x;
        float d1 = a.y - b.y;
        float d2 = a.z - b.z;
        float d3 = a.w - b.w;
        acc = fmaf(d0, d0, acc);
        acc = fmaf(d1, d1, acc);
        acc = fmaf(d2, d2, acc);
        acc = fmaf(d3, d3, acc);
    }

    // warp reduce
    #pragma unroll
    for (int off = 16; off > 0; off >>= 1)
        acc += __shfl_xor_sync(0xFFFFFFFFu, acc, off);

    __shared__ float warp_sums[TPB_ / 32];   // 9 warps
    const int lane = threadIdx.x & 31;
    const int wid  = threadIdx.x >> 5;
    if (lane == 0) warp_sums[wid] = acc;
    __syncthreads();

    if (threadIdx.x == 0) {
        float s = 0.0f;
        #pragma unroll
        for (int w9 = 0; w9 < TPB_ / 32; w9++) s += warp_sums[w9];
        const int b = bj / J_;
        const int j = bj - b * J_;
        g_partials[j * B_ + b] = s * w_early * w_early;   // transposed store
    }
}

// ---------------------------------------------------------------------------
// Kernel B (PDL secondary): 17 warps, one per joint; contiguous float4 loads.
// topk prefetched before the parked wait (independent of A's data).
// ---------------------------------------------------------------------------
__global__ __launch_bounds__(544) void jmse_final_kernel(
    const int* __restrict__ topk_ptr,
    float* __restrict__ result)
{
    __shared__ float losses[J_];
    __shared__ int   s_k;
    const int wid  = threadIdx.x >> 5;   // 0..16
    const int lane = threadIdx.x & 31;

    // Prefetch top_k while parked: does not depend on kernel A's writes.
    if (threadIdx.x == 0) s_k = *topk_ptr;

    // Park until primary grid completes; its writes are then visible.
    asm volatile("griddepcontrol.wait;");

    if (wid < J_) {
        // 256 floats per joint = 64 float4, 2 per lane
        const float4* p4 = (const float4*)&g_partials[wid * B_];
        float4 a = p4[lane];
        float4 b = p4[lane + 32];
        float s = (a.x + a.y) + (a.z + a.w) + (b.x + b.y) + (b.z + b.w);
        #pragma unroll
        for (int off = 16; off > 0; off >>= 1)
            s += __shfl_xor_sync(0xFFFFFFFFu, s, off);
        if (lane == 0)
            losses[wid] = s * (1.0f / ((float)B_ * (float)HW_));
    }
    __syncthreads();

    if (threadIdx.x == 0) {
        const int k = s_k;
        float v[J_];
        #pragma unroll
        for (int j = 0; j < J_; j++) v[j] = losses[j];
        float sum = 0.0f;
        for (int s = 0; s < k; s++) {
            int   best_i = 0;
            float best_v = v[0];
            #pragma unroll
            for (int j = 1; j < J_; j++)
                if (v[j] > best_v) { best_v = v[j]; best_i = j; }
            sum += best_v;
            v[best_i] = -3.402823466e38f;
        }
        result[0] = sum / (float)k;
    }
}

// ---------------------------------------------------------------------------
extern "C" void kernel_launch(void* const* d_in, const int* in_sizes, int n_in,
                              void* d_out, int out_size)
{
    const float* out_t = (const float*)d_in[0];
    const float* tgt_t = (const float*)d_in[1];
    const float* wgt_t = (const float*)d_in[2];
    const int*   topk  = (const int*)d_in[3];
    float* res = (float*)d_out;

    jmse_partial_kernel<<<BJ_, TPB_>>>(out_t, tgt_t, wgt_t);

    cudaLaunchConfig_t cfg = {};
    cfg.gridDim  = dim3(1, 1, 1);
    cfg.blockDim = dim3(544, 1, 1);
    cfg.dynamicSmemBytes = 0;
    cfg.stream = 0;
    cudaLaunchAttribute attr[1];
    attr[0].id = cudaLaunchAttributeProgrammaticStreamSerialization;
    attr[0].val.programmaticStreamSerializationAllowed = 1;
    cfg.attrs = attr;
    cfg.numAttrs = 1;
    cudaLaunchKernelEx(&cfg, jmse_final_kernel, topk, res);
}

// round 12
// speedup vs baseline: 1.1558x; 1.0503x over previous
#include <cuda_runtime.h>

// Problem constants (from reference setup_inputs)
#define B_    256
#define J_    17
#define HW_   6912            // 96*72
#define V4_   (HW_ / 4)       // 1728 float4 per (b,j) slice
#define BJ_   (B_ * J_)       // 4352
#define TPB_  288             // 1728 / 288 = exactly 6 iterations, no ragged tail

// Scratch: transposed partials, g_partials[j * B_ + b] (contiguous per joint)
__device__ float g_partials[BJ_];

// ---------------------------------------------------------------------------
// Kernel A: one block per (b,j) slice, 288 threads, exact 6-iter unrolled
// stream with evict-first (__ldcs) loads. PDL trigger fired at entry;
// weight load hoisted to overlap the stream.
// ---------------------------------------------------------------------------
__global__ __launch_bounds__(TPB_) void jmse_partial_kernel(
    const float* __restrict__ out,
    const float* __restrict__ tgt,
    const float* __restrict__ wgt)
{
    asm volatile("griddepcontrol.launch_dependents;");

    const int bj = blockIdx.x;

    // Hoisted scalar weight load: resolved long before the epilogue.
    float w_early = 0.0f;
    if (threadIdx.x == 0) w_early = __ldg(&wgt[bj]);

    const size_t base = (size_t)bj * HW_;
    const float4* __restrict__ o4 = (const float4*)(out + base);
    const float4* __restrict__ t4 = (const float4*)(tgt + base);

    // Two independent accumulator chains (even/odd unroll steps).
    float acc0 = 0.0f, acc1 = 0.0f;
    #pragma unroll
    for (int k = 0; k < 6; k++) {          // exact: 6 * 288 = 1728
        const int i = threadIdx.x + k * TPB_;
        float4 a = __ldcs(o4 + i);         // single-use stream: evict-first
        float4 b = __ldcs(t4 + i);
        float d0 = a.x - b.x;
        float d1 = a.y - b.y;
        float d2 = a.z - b.z;
        float d3 = a.w - b.w;
        if (k & 1) {
            acc1 = fmaf(d0, d0, acc1);
            acc1 = fmaf(d1, d1, acc1);
            acc1 = fmaf(d2, d2, acc1);
            acc1 = fmaf(d3, d3, acc1);
        } else {
            acc0 = fmaf(d0, d0, acc0);
            acc0 = fmaf(d1, d1, acc0);
            acc0 = fmaf(d2, d2, acc0);
            acc0 = fmaf(d3, d3, acc0);
        }
    }
    float acc = acc0 + acc1;

    // warp reduce
    #pragma unroll
    for (int off = 16; off > 0; off >>= 1)
        acc += __shfl_xor_sync(0xFFFFFFFFu, acc, off);

    __shared__ float warp_sums[TPB_ / 32];   // 9 warps
    const int lane = threadIdx.x & 31;
    const int wid  = threadIdx.x >> 5;
    if (lane == 0) warp_sums[wid] = acc;
    __syncthreads();

    if (threadIdx.x == 0) {
        float s = 0.0f;
        #pragma unroll
        for (int w9 = 0; w9 < TPB_ / 32; w9++) s += warp_sums[w9];
        const int b = bj / J_;
        const int j = bj - b * J_;
        g_partials[j * B_ + b] = s * w_early * w_early;   // transposed store
    }
}

// ---------------------------------------------------------------------------
// Kernel B (PDL secondary): 17 warps, one per joint; contiguous float4 loads.
// topk prefetched before the parked wait (independent of A's data).
// ---------------------------------------------------------------------------
__global__ __launch_bounds__(544) void jmse_final_kernel(
    const int* __restrict__ topk_ptr,
    float* __restrict__ result)
{
    __shared__ float losses[J_];
    __shared__ int   s_k;
    const int wid  = threadIdx.x >> 5;   // 0..16
    const int lane = threadIdx.x & 31;

    // Prefetch top_k while parked: does not depend on kernel A's writes.
    if (threadIdx.x == 0) s_k = *topk_ptr;

    // Park until primary grid completes; its writes are then visible.
    asm volatile("griddepcontrol.wait;");

    if (wid < J_) {
        // 256 floats per joint = 64 float4, 2 per lane
        const float4* p4 = (const float4*)&g_partials[wid * B_];
        float4 a = p4[lane];
        float4 b = p4[lane + 32];
        float s = (a.x + a.y) + (a.z + a.w) + (b.x + b.y) + (b.z + b.w);
        #pragma unroll
        for (int off = 16; off > 0; off >>= 1)
            s += __shfl_xor_sync(0xFFFFFFFFu, s, off);
        if (lane == 0)
            losses[wid] = s * (1.0f / ((float)B_ * (float)HW_));
    }
    __syncthreads();

    if (threadIdx.x == 0) {
        const int k = s_k;
        float v[J_];
        #pragma unroll
        for (int j = 0; j < J_; j++) v[j] = losses[j];
        float sum = 0.0f;
        for (int s = 0; s < k; s++) {
            int   best_i = 0;
            float best_v = v[0];
            #pragma unroll
            for (int j = 1; j < J_; j++)
                if (v[j] > best_v) { best_v = v[j]; best_i = j; }
            sum += best_v;
            v[best_i] = -3.402823466e38f;
        }
        result[0] = sum / (float)k;
    }
}

// ---------------------------------------------------------------------------
extern "C" void kernel_launch(void* const* d_in, const int* in_sizes, int n_in,
                              void* d_out, int out_size)
{
    const float* out_t = (const float*)d_in[0];
    const float* tgt_t = (const float*)d_in[1];
    const float* wgt_t = (const float*)d_in[2];
    const int*   topk  = (const int*)d_in[3];
    float* res = (float*)d_out;

    jmse_partial_kernel<<<BJ_, TPB_>>>(out_t, tgt_t, wgt_t);

    cudaLaunchConfig_t cfg = {};
    cfg.gridDim  = dim3(1, 1, 1);
    cfg.blockDim = dim3(544, 1, 1);
    cfg.dynamicSmemBytes = 0;
    cfg.stream = 0;
    cudaLaunchAttribute attr[1];
    attr[0].id = cudaLaunchAttributeProgrammaticStreamSerialization;
    attr[0].val.programmaticStreamSerializationAllowed = 1;
    cfg.attrs = attr;
    cfg.numAttrs = 1;
    cudaLaunchKernelEx(&cfg, jmse_final_kernel, topk, res);
}